// round 14
// baseline (speedup 1.0000x reference)
#include <cuda_runtime.h>

#define NTH 256
#define PROB_PER_BLK (NTH * 4)     // 1024
#define MAXBLK 4096

typedef unsigned long long u64;

__device__ double g_part[11 * MAXBLK];
__device__ double g_osum6[6];      // stage-A reduced sums o_0..o_5
__device__ int    g_arriveA;       // monotone across graph replays
__device__ int    g_arriveB;
__device__ int    g_flagA;         // (epochA+1)*16 + code ; code: 0..4 = K, 15 = continue
__device__ int    g_flagB;         // (epochB+1)*16 + (K-5) ; K in 5..10

// ---------- packed f32x2 primitives (sm_100+) ----------
__device__ __forceinline__ u64 fma2(u64 a, u64 b, u64 c) {
    u64 d; asm("fma.rn.f32x2 %0, %1, %2, %3;" : "=l"(d) : "l"(a), "l"(b), "l"(c)); return d;
}
__device__ __forceinline__ u64 mul2(u64 a, u64 b) {
    u64 d; asm("mul.rn.f32x2 %0, %1, %2;" : "=l"(d) : "l"(a), "l"(b)); return d;
}
__device__ __forceinline__ u64 add2(u64 a, u64 b) {
    u64 d; asm("add.rn.f32x2 %0, %1, %2;" : "=l"(d) : "l"(a), "l"(b)); return d;
}
__device__ __forceinline__ u64 neg2(u64 a) { return a ^ 0x8000000080000000ull; }
__device__ __forceinline__ u64 sub2(u64 a, u64 b) { return add2(a, neg2(b)); }

__device__ __forceinline__ u64 pack2(float lo, float hi) {
    u64 d; asm("mov.b64 %0, {%1, %2};" : "=l"(d) : "f"(lo), "f"(hi)); return d;
}
__device__ __forceinline__ void unpack2(u64 a, float& lo, float& hi) {
    asm("mov.b64 {%0, %1}, %2;" : "=f"(lo), "=f"(hi) : "l"(a));
}
__device__ __forceinline__ float frcp(float a) {
    float r; asm("rcp.approx.f32 %0, %1;" : "=f"(r) : "f"(a)); return r;
}
__device__ __forceinline__ u64 rcp2(u64 a) {
    float lo, hi; unpack2(a, lo, hi);
    return pack2(frcp(lo), frcp(hi));
}

#define C3   0x4040000040400000ull   // {3.0f, 3.0f}
#define C2   0x4000000040000000ull   // {2.0f, 2.0f}
#define ONE2 0x3F8000003F800000ull   // {1.0f, 1.0f}

// y-free packed GN step, single rcp on the critical path (Bv-scaled Schur).
// Carries (x1,x2,S1,S2) + affine y-coeffs (al,be): y_t = al*y0 + be.
// Returns packed objective at the INPUT state: 3Q + 2(P1*S1 + S2) + Q*S2.
__device__ __forceinline__ u64 gn2(u64& x1, u64& x2, u64& S1, u64& S2,
                                   u64& al, u64& be) {
    u64 Q  = fma2(x1, x1, mul2(x2, x2));
    u64 P1 = add2(x1, x2);
    u64 obj = fma2(Q, S2, fma2(C2, fma2(P1, S1, S2), mul2(C3, Q)));

    u64 A  = add2(S2, C3);
    u64 Bv = add2(Q, C2);
    u64 t  = rcp2(Bv);                  // parallel to the M/det chain

    u64 q1 = fma2(S1, x1, C3);
    u64 q2 = fma2(S1, x2, C3);
    u64 a1 = fma2(S2, x1, S1);
    u64 a2 = fma2(S2, x2, S1);

    u64 cc11 = fma2(a1, x1, q1);
    u64 cc12 = fma2(a1, x2, q1);
    u64 cc22 = fma2(a2, x2, q2);

    u64 AB  = mul2(A, Bv);
    u64 m11 = sub2(AB, cc11);
    u64 m22 = sub2(AB, cc22);

    u64 B3  = mul2(C3, Bv);
    u64 P1n = neg2(P1);
    u64 r1 = fma2(B3, x1, mul2(P1n, q1));
    u64 r2 = fma2(B3, x2, mul2(P1n, q2));

    u64 detM = fma2(m11, m22, neg2(mul2(cc12, cc12)));
    u64 i    = rcp2(detM);              // the ONE rcp on the critical path

    u64 ux1 = mul2(fma2(m22, r1, mul2(cc12, r2)), i);
    u64 ux2 = mul2(fma2(m11, r2, mul2(cc12, r1)), i);

    u64 Su = add2(ux1, ux2);
    u64 xu = fma2(x1, ux1, mul2(x2, ux2));   // uses OLD x
    x1 = sub2(x1, ux1);
    x2 = sub2(x2, ux2);

    u64 c   = add2(Su, P1n);
    u64 txu = mul2(t, xu);
    u64 tc  = mul2(t, c);

    al = mul2(txu, al);
    be = fma2(txu, be, tc);

    u64 S1n = fma2(txu, S1, mul2(C3, tc));
    u64 S2n = fma2(txu, fma2(txu, S2, mul2(mul2(C2, tc), S1)),
                   mul2(C3, mul2(tc, tc)));
    S1 = S1n; S2 = S2n;
    return obj;
}

__device__ __forceinline__ u64 obj_state(u64 x1, u64 x2, u64 S1, u64 S2) {
    u64 Q  = fma2(x1, x1, mul2(x2, x2));
    u64 P1 = add2(x1, x2);
    return fma2(Q, S2, fma2(C2, fma2(P1, S1, S2), mul2(C3, Q)));
}

__device__ __forceinline__ void load_chain(const float* __restrict__ xin,
                                           const float* __restrict__ yin,
                                           int b0, int b1, int B,
                                           u64& x1, u64& x2, u64& S1, u64& S2,
                                           u64& y1, u64& y2, u64& y3,
                                           bool& v0, bool& v1) {
    v0 = (b0 < B); v1 = (b1 < B);
    float ax1 = 1.f, ax2 = 0.f, ay1 = 1.f, ay2 = 0.f, ay3 = 0.f;
    float bx1 = 1.f, bx2 = 0.f, by1 = 1.f, by2 = 0.f, by3 = 0.f;
    if (v0) {
        float2 xv = *reinterpret_cast<const float2*>(xin + 2 * b0);
        ax1 = xv.x; ax2 = xv.y;
        ay1 = yin[3 * b0]; ay2 = yin[3 * b0 + 1]; ay3 = yin[3 * b0 + 2];
    }
    if (v1) {
        float2 xv = *reinterpret_cast<const float2*>(xin + 2 * b1);
        bx1 = xv.x; bx2 = xv.y;
        by1 = yin[3 * b1]; by2 = yin[3 * b1 + 1]; by3 = yin[3 * b1 + 2];
    }
    x1 = pack2(ax1, bx1); x2 = pack2(ax2, bx2);
    y1 = pack2(ay1, by1); y2 = pack2(ay2, by2); y3 = pack2(ay3, by3);
    S1 = add2(add2(y1, y2), y3);
    S2 = fma2(y1, y1, fma2(y2, y2, mul2(y3, y3)));
}

__device__ __forceinline__ float masked_sum(u64 o, bool v0, bool v1) {
    float lo, hi; unpack2(o, lo, hi);
    return (v0 ? lo : 0.f) + (v1 ? hi : 0.f);
}

__device__ __forceinline__ void store_chain(float* __restrict__ out, int B,
                                            int b0, int b1, bool v0, bool v1,
                                            u64 x1, u64 x2, u64 y1, u64 y2, u64 y3) {
    float lx1, lx2, ly1, ly2, ly3, hx1, hx2, hy1, hy2, hy3;
    unpack2(x1, lx1, hx1); unpack2(x2, lx2, hx2);
    unpack2(y1, ly1, hy1); unpack2(y2, ly2, hy2); unpack2(y3, ly3, hy3);
    if (v0) {
        out[2 * b0] = lx1; out[2 * b0 + 1] = lx2;
        out[2 * B + 3 * b0] = ly1; out[2 * B + 3 * b0 + 1] = ly2; out[2 * B + 3 * b0 + 2] = ly3;
    }
    if (v1) {
        out[2 * b1] = hx1; out[2 * b1 + 1] = hx2;
        out[2 * B + 3 * b1] = hy1; out[2 * B + 3 * b1 + 1] = hy2; out[2 * B + 3 * b1 + 2] = hy3;
    }
}

// Two-stage fused kernel. Stage A: 5 steps + global decide over o_0..o_5; if a
// reject is in the prefix (K<=4), emit from anchor-3/input and stop. Stage B:
// steps 6..10 + second decide (K in 5..10), anchor-7 resume.
// 256 blocks all resident (launch_bounds(256,2) -> 296 capacity) -> polls safe.
__global__ void __launch_bounds__(NTH, 2)
k_all(const float* __restrict__ xin, const float* __restrict__ yin,
      float* __restrict__ out, int B, int nblk) {
    int tid  = threadIdx.x;
    int base = blockIdx.x * PROB_PER_BLK + tid;
    int b0 = base, b1 = base + NTH, b2 = base + 2 * NTH, b3 = base + 3 * NTH;
    int lane = tid & 31;
    int wid  = tid >> 5;

    __shared__ float4 anch[2][4 * NTH];   // 32KB: (x1,x2,al,be) after steps 3, 7
    __shared__ float  sm[(NTH / 32)][6];
    __shared__ double osum[6];
    __shared__ int    s_epoch, s_is_last, s_code;

    // ---- stage A: 5 GN steps, 2 independent packed chains ----
    u64 Ax1, Ax2, AS1, AS2, Aal = ONE2, Abe = 0;
    u64 Bx1, Bx2, BS1, BS2, Bal = ONE2, Bbe = 0;
    u64 Ay1, Ay2, Ay3, By1, By2, By3;
    bool va0, va1, vb0, vb1;
    load_chain(xin, yin, b0, b1, B, Ax1, Ax2, AS1, AS2, Ay1, Ay2, Ay3, va0, va1);
    load_chain(xin, yin, b2, b3, B, Bx1, Bx2, BS1, BS2, By1, By2, By3, vb0, vb1);

    float oA[6];
#pragma unroll
    for (int t = 0; t < 5; t++) {
        u64 oa = gn2(Ax1, Ax2, AS1, AS2, Aal, Abe);
        u64 ob = gn2(Bx1, Bx2, BS1, BS2, Bal, Bbe);
        oA[t] = masked_sum(oa, va0, va1) + masked_sum(ob, vb0, vb1);
        if (t == 2) {                     // state after step 3
            float p, q, r, s, p2, q2, r2, s2;
            unpack2(Ax1, p, p2); unpack2(Ax2, q, q2);
            unpack2(Aal, r, r2); unpack2(Abe, s, s2);
            anch[0][tid]           = make_float4(p,  q,  r,  s);
            anch[0][tid + NTH]     = make_float4(p2, q2, r2, s2);
            unpack2(Bx1, p, p2); unpack2(Bx2, q, q2);
            unpack2(Bal, r, r2); unpack2(Bbe, s, s2);
            anch[0][tid + 2 * NTH] = make_float4(p,  q,  r,  s);
            anch[0][tid + 3 * NTH] = make_float4(p2, q2, r2, s2);
        }
    }
    oA[5] = masked_sum(obj_state(Ax1, Ax2, AS1, AS2), va0, va1)
          + masked_sum(obj_state(Bx1, Bx2, BS1, BS2), vb0, vb1);

    // block reduction rows 0..5
#pragma unroll
    for (int t = 0; t < 6; t++) {
        float v = oA[t];
#pragma unroll
        for (int off = 16; off > 0; off >>= 1)
            v += __shfl_down_sync(0xffffffffu, v, off);
        if (lane == 0) sm[wid][t] = v;
    }
    __syncthreads();
    if (wid == 0) {
#pragma unroll
        for (int t = 0; t < 6; t++) {
            float w = (lane < (NTH / 32)) ? sm[lane][t] : 0.f;
#pragma unroll
            for (int off = 4; off > 0; off >>= 1)
                w += __shfl_down_sync(0xffffffffu, w, off);
            if (lane == 0) g_part[t * MAXBLK + blockIdx.x] = (double)w;
        }
    }

    // arrival A; last block decides the prefix
    __threadfence();
    if (tid == 0) {
        int old = atomicAdd(&g_arriveA, 1);
        s_epoch   = old / nblk;
        s_is_last = ((old % nblk) == (nblk - 1));
    }
    __syncthreads();
    int epochA = s_epoch;

    if (s_is_last) {
        if (wid == 0) {
            for (int t = lane; t < 6; t += 32) {
                double s = 0.0;
                for (int i = 0; i < nblk; i++) s += g_part[t * MAXBLK + i];
                osum[t] = s;
            }
        }
        // parallel version: one warp per row would be faster, but 6*256 loads is tiny
        __syncthreads();
        if (tid == 0) {
            int code = 15;                       // continue sentinel
            double prev = osum[0];
            for (int t = 1; t <= 5; t++) {
                if (!(osum[t] < prev)) { code = t - 1; break; }
                prev = osum[t];
            }
            for (int t = 0; t < 6; t++) g_osum6[t] = osum[t];
            __threadfence();
            atomicExch(&g_flagA, (epochA + 1) * 16 + code);
        }
    }

    // poll flag A
    {
        int target = (epochA + 1) * 16;
        if (tid == 0) {
            int f = *(volatile int*)&g_flagA;
            int spins = 0;
            while (f < target && spins < 400000) {
                __nanosleep(32);
                f = *(volatile int*)&g_flagA;
                spins++;
            }
            s_code = (f >= target) ? (f - target) : 15;   // timeout -> continue
        }
        __syncthreads();
    }
    int K;
    if (s_code <= 4) {
        K = s_code;
    } else {
        // ---- stage B: steps 6..10 ----
        float oB[5];
#pragma unroll
        for (int e = 0; e < 5; e++) {
            u64 oa = gn2(Ax1, Ax2, AS1, AS2, Aal, Abe);
            u64 ob = gn2(Bx1, Bx2, BS1, BS2, Bal, Bbe);
            if (e > 0)
                oB[e - 1] = masked_sum(oa, va0, va1) + masked_sum(ob, vb0, vb1);
            if (e == 1) {                 // state after step 7
                float p, q, r, s, p2, q2, r2, s2;
                unpack2(Ax1, p, p2); unpack2(Ax2, q, q2);
                unpack2(Aal, r, r2); unpack2(Abe, s, s2);
                anch[1][tid]           = make_float4(p,  q,  r,  s);
                anch[1][tid + NTH]     = make_float4(p2, q2, r2, s2);
                unpack2(Bx1, p, p2); unpack2(Bx2, q, q2);
                unpack2(Bal, r, r2); unpack2(Bbe, s, s2);
                anch[1][tid + 2 * NTH] = make_float4(p,  q,  r,  s);
                anch[1][tid + 3 * NTH] = make_float4(p2, q2, r2, s2);
            }
        }
        oB[4] = masked_sum(obj_state(Ax1, Ax2, AS1, AS2), va0, va1)
              + masked_sum(obj_state(Bx1, Bx2, BS1, BS2), vb0, vb1);

        __syncthreads();   // sm[] reuse
#pragma unroll
        for (int t = 0; t < 5; t++) {
            float v = oB[t];
#pragma unroll
            for (int off = 16; off > 0; off >>= 1)
                v += __shfl_down_sync(0xffffffffu, v, off);
            if (lane == 0) sm[wid][t] = v;
        }
        __syncthreads();
        if (wid == 0) {
#pragma unroll
            for (int t = 0; t < 5; t++) {
                float w = (lane < (NTH / 32)) ? sm[lane][t] : 0.f;
#pragma unroll
                for (int off = 4; off > 0; off >>= 1)
                    w += __shfl_down_sync(0xffffffffu, w, off);
                if (lane == 0) g_part[(6 + t) * MAXBLK + blockIdx.x] = (double)w;
            }
        }

        __threadfence();
        if (tid == 0) {
            int old = atomicAdd(&g_arriveB, 1);
            s_epoch   = old / nblk;
            s_is_last = ((old % nblk) == (nblk - 1));
        }
        __syncthreads();
        int epochB = s_epoch;

        if (s_is_last) {
            if (wid == 0) {
                for (int t = lane; t < 5; t += 32) {
                    double s = 0.0;
                    for (int i = 0; i < nblk; i++) s += g_part[(6 + t) * MAXBLK + i];
                    osum[t] = s;
                }
            }
            __syncthreads();
            if (tid == 0) {
                __threadfence();
                double prev = g_osum6[5];
                int Kd = 10;
                for (int t = 0; t < 5; t++) {        // rows = o_6..o_10
                    if (!(osum[t] < prev)) { Kd = 5 + t; break; }
                    prev = osum[t];
                }
                atomicExch(&g_flagB, (epochB + 1) * 16 + (Kd - 5));
            }
        }

        {
            int target = (epochB + 1) * 16;
            if (tid == 0) {
                int f = *(volatile int*)&g_flagB;
                int spins = 0;
                while (f < target && spins < 400000) {
                    __nanosleep(32);
                    f = *(volatile int*)&g_flagB;
                    spins++;
                }
                s_code = (f >= target) ? (f - target) : 5;   // timeout -> K=10
            }
            __syncthreads();
        }
        K = 5 + s_code;
    }

    // ---- phase 2: emit s_K ----
    if (K < 10) {
        int extra;
        if (K >= 7) {
            float4 cA0 = anch[1][tid],           cA1 = anch[1][tid + NTH];
            float4 cB0 = anch[1][tid + 2 * NTH], cB1 = anch[1][tid + 3 * NTH];
            Ax1 = pack2(cA0.x, cA1.x); Ax2 = pack2(cA0.y, cA1.y);
            Aal = pack2(cA0.z, cA1.z); Abe = pack2(cA0.w, cA1.w);
            Bx1 = pack2(cB0.x, cB1.x); Bx2 = pack2(cB0.y, cB1.y);
            Bal = pack2(cB0.z, cB1.z); Bbe = pack2(cB0.w, cB1.w);
            extra = K - 7;
        } else if (K >= 3) {
            float4 cA0 = anch[0][tid],           cA1 = anch[0][tid + NTH];
            float4 cB0 = anch[0][tid + 2 * NTH], cB1 = anch[0][tid + 3 * NTH];
            Ax1 = pack2(cA0.x, cA1.x); Ax2 = pack2(cA0.y, cA1.y);
            Aal = pack2(cA0.z, cA1.z); Abe = pack2(cA0.w, cA1.w);
            Bx1 = pack2(cB0.x, cB1.x); Bx2 = pack2(cB0.y, cB1.y);
            Bal = pack2(cB0.z, cB1.z); Bbe = pack2(cB0.w, cB1.w);
            extra = K - 3;
        } else {
            u64 w1, w2, w3, ws1, ws2; bool t0, t1;
            load_chain(xin, yin, b0, b1, B, Ax1, Ax2, ws1, ws2, w1, w2, w3, t0, t1);
            load_chain(xin, yin, b2, b3, B, Bx1, Bx2, ws1, ws2, w1, w2, w3, t0, t1);
            Aal = ONE2; Abe = 0; Bal = ONE2; Bbe = 0;
            extra = K;
        }
        if (extra > 0) {
            u64 ty1 = fma2(Aal, Ay1, Abe), ty2 = fma2(Aal, Ay2, Abe), ty3 = fma2(Aal, Ay3, Abe);
            AS1 = add2(add2(ty1, ty2), ty3);
            AS2 = fma2(ty1, ty1, fma2(ty2, ty2, mul2(ty3, ty3)));
            ty1 = fma2(Bal, By1, Bbe); ty2 = fma2(Bal, By2, Bbe); ty3 = fma2(Bal, By3, Bbe);
            BS1 = add2(add2(ty1, ty2), ty3);
            BS2 = fma2(ty1, ty1, fma2(ty2, ty2, mul2(ty3, ty3)));
            for (int e = 0; e < extra; e++) {
                gn2(Ax1, Ax2, AS1, AS2, Aal, Abe);
                gn2(Bx1, Bx2, BS1, BS2, Bal, Bbe);
            }
        }
    }

    Ay1 = fma2(Aal, Ay1, Abe); Ay2 = fma2(Aal, Ay2, Abe); Ay3 = fma2(Aal, Ay3, Abe);
    By1 = fma2(Bal, By1, Bbe); By2 = fma2(Bal, By2, Bbe); By3 = fma2(Bal, By3, Bbe);
    store_chain(out, B, b0, b1, va0, va1, Ax1, Ax2, Ay1, Ay2, Ay3);
    store_chain(out, B, b2, b3, vb0, vb1, Bx1, Bx2, By1, By2, By3);
}

extern "C" void kernel_launch(void* const* d_in, const int* in_sizes, int n_in,
                              void* d_out, int out_size) {
    const float* x = (const float*)d_in[0];   // (B,1,2) float32
    const float* y = (const float*)d_in[1];   // (B,3,1) float32
    int B = in_sizes[0] / 2;
    int nblk = (B + PROB_PER_BLK - 1) / PROB_PER_BLK;   // 256 for B=262144
    if (nblk > MAXBLK) nblk = MAXBLK;

    k_all<<<nblk, NTH>>>(x, y, (float*)d_out, B, nblk);
}

// round 15
// speedup vs baseline: 1.1967x; 1.1967x over previous
#include <cuda_runtime.h>

#define NTH 256
#define PROB_PER_BLK (NTH * 4)     // 1024
#define MAXBLK 4096

typedef unsigned long long u64;

__device__ double g_part[11 * MAXBLK];
__device__ int    g_arrive;   // monotone across graph replays
__device__ int    g_flag;     // monotone: (epoch+1)*16 + K ; K = g_flag & 15

// ---------- packed f32x2 primitives (sm_100+) ----------
__device__ __forceinline__ u64 fma2(u64 a, u64 b, u64 c) {
    u64 d; asm("fma.rn.f32x2 %0, %1, %2, %3;" : "=l"(d) : "l"(a), "l"(b), "l"(c)); return d;
}
__device__ __forceinline__ u64 mul2(u64 a, u64 b) {
    u64 d; asm("mul.rn.f32x2 %0, %1, %2;" : "=l"(d) : "l"(a), "l"(b)); return d;
}
__device__ __forceinline__ u64 add2(u64 a, u64 b) {
    u64 d; asm("add.rn.f32x2 %0, %1, %2;" : "=l"(d) : "l"(a), "l"(b)); return d;
}
__device__ __forceinline__ u64 neg2(u64 a) { return a ^ 0x8000000080000000ull; }
__device__ __forceinline__ u64 sub2(u64 a, u64 b) { return add2(a, neg2(b)); }

__device__ __forceinline__ u64 pack2(float lo, float hi) {
    u64 d; asm("mov.b64 %0, {%1, %2};" : "=l"(d) : "f"(lo), "f"(hi)); return d;
}
__device__ __forceinline__ void unpack2(u64 a, float& lo, float& hi) {
    asm("mov.b64 {%0, %1}, %2;" : "=f"(lo), "=f"(hi) : "l"(a));
}
__device__ __forceinline__ float frcp(float a) {
    float r; asm("rcp.approx.f32 %0, %1;" : "=f"(r) : "f"(a)); return r;
}
__device__ __forceinline__ u64 rcp2(u64 a) {
    float lo, hi; unpack2(a, lo, hi);
    return pack2(frcp(lo), frcp(hi));
}

#define C3   0x4040000040400000ull   // {3.0f, 3.0f}
#define C2   0x4000000040000000ull   // {2.0f, 2.0f}
#define ONE2 0x3F8000003F800000ull   // {1.0f, 1.0f}

// y-free packed GN step, single rcp on the critical path (Bv-scaled Schur).
// Carries (x1,x2,S1,S2) + affine y-coeffs (al,be): y_t = al*y0 + be.
// Returns packed objective at the INPUT state: 3Q + 2(P1*S1 + S2) + Q*S2.
__device__ __forceinline__ u64 gn2(u64& x1, u64& x2, u64& S1, u64& S2,
                                   u64& al, u64& be) {
    u64 Q  = fma2(x1, x1, mul2(x2, x2));
    u64 P1 = add2(x1, x2);
    u64 obj = fma2(Q, S2, fma2(C2, fma2(P1, S1, S2), mul2(C3, Q)));

    u64 A  = add2(S2, C3);
    u64 Bv = add2(Q, C2);
    u64 t  = rcp2(Bv);                  // parallel to the M/det chain

    u64 q1 = fma2(S1, x1, C3);
    u64 q2 = fma2(S1, x2, C3);
    u64 a1 = fma2(S2, x1, S1);
    u64 a2 = fma2(S2, x2, S1);

    u64 cc11 = fma2(a1, x1, q1);
    u64 cc12 = fma2(a1, x2, q1);
    u64 cc22 = fma2(a2, x2, q2);

    u64 AB  = mul2(A, Bv);
    u64 m11 = sub2(AB, cc11);
    u64 m22 = sub2(AB, cc22);

    u64 B3  = mul2(C3, Bv);
    u64 P1n = neg2(P1);
    u64 r1 = fma2(B3, x1, mul2(P1n, q1));
    u64 r2 = fma2(B3, x2, mul2(P1n, q2));

    u64 detM = fma2(m11, m22, neg2(mul2(cc12, cc12)));
    u64 i    = rcp2(detM);              // the ONE rcp on the critical path

    u64 ux1 = mul2(fma2(m22, r1, mul2(cc12, r2)), i);
    u64 ux2 = mul2(fma2(m11, r2, mul2(cc12, r1)), i);

    u64 Su = add2(ux1, ux2);
    u64 xu = fma2(x1, ux1, mul2(x2, ux2));   // uses OLD x
    x1 = sub2(x1, ux1);
    x2 = sub2(x2, ux2);

    u64 c   = add2(Su, P1n);
    u64 txu = mul2(t, xu);
    u64 tc  = mul2(t, c);

    al = mul2(txu, al);
    be = fma2(txu, be, tc);

    u64 S1n = fma2(txu, S1, mul2(C3, tc));
    u64 S2n = fma2(txu, fma2(txu, S2, mul2(mul2(C2, tc), S1)),
                   mul2(C3, mul2(tc, tc)));
    S1 = S1n; S2 = S2n;
    return obj;
}

__device__ __forceinline__ u64 obj_state(u64 x1, u64 x2, u64 S1, u64 S2) {
    u64 Q  = fma2(x1, x1, mul2(x2, x2));
    u64 P1 = add2(x1, x2);
    return fma2(Q, S2, fma2(C2, fma2(P1, S1, S2), mul2(C3, Q)));
}

// Load x pair (packed). Validity by index.
__device__ __forceinline__ void load_x(const float* __restrict__ xin,
                                       int b0, int b1, int B,
                                       u64& x1, u64& x2, bool& v0, bool& v1) {
    v0 = (b0 < B); v1 = (b1 < B);
    float ax1 = 1.f, ax2 = 0.f, bx1 = 1.f, bx2 = 0.f;
    if (v0) { float2 xv = *reinterpret_cast<const float2*>(xin + 2 * b0); ax1 = xv.x; ax2 = xv.y; }
    if (v1) { float2 xv = *reinterpret_cast<const float2*>(xin + 2 * b1); bx1 = xv.x; bx2 = xv.y; }
    x1 = pack2(ax1, bx1); x2 = pack2(ax2, bx2);
}
__device__ __forceinline__ void load_y(const float* __restrict__ yin,
                                       int b0, int b1, int B,
                                       u64& y1, u64& y2, u64& y3) {
    float ay1 = 1.f, ay2 = 0.f, ay3 = 0.f, by1 = 1.f, by2 = 0.f, by3 = 0.f;
    if (b0 < B) { ay1 = yin[3 * b0]; ay2 = yin[3 * b0 + 1]; ay3 = yin[3 * b0 + 2]; }
    if (b1 < B) { by1 = yin[3 * b1]; by2 = yin[3 * b1 + 1]; by3 = yin[3 * b1 + 2]; }
    y1 = pack2(ay1, by1); y2 = pack2(ay2, by2); y3 = pack2(ay3, by3);
}

__device__ __forceinline__ float masked_sum(u64 o, bool v0, bool v1) {
    float lo, hi; unpack2(o, lo, hi);
    return (v0 ? lo : 0.f) + (v1 ? hi : 0.f);
}

__device__ __forceinline__ void store_chain(float* __restrict__ out, int B,
                                            int b0, int b1, bool v0, bool v1,
                                            u64 x1, u64 x2, u64 y1, u64 y2, u64 y3) {
    float lx1, lx2, ly1, ly2, ly3, hx1, hx2, hy1, hy2, hy3;
    unpack2(x1, lx1, hx1); unpack2(x2, lx2, hx2);
    unpack2(y1, ly1, hy1); unpack2(y2, ly2, hy2); unpack2(y3, ly3, hy3);
    if (v0) {
        out[2 * b0] = lx1; out[2 * b0 + 1] = lx2;
        out[2 * B + 3 * b0] = ly1; out[2 * B + 3 * b0 + 1] = ly2; out[2 * B + 3 * b0 + 2] = ly3;
    }
    if (v1) {
        out[2 * b1] = hx1; out[2 * b1 + 1] = hx2;
        out[2 * B + 3 * b1] = hy1; out[2 * B + 3 * b1 + 1] = hy2; out[2 * B + 3 * b1 + 2] = hy3;
    }
}

// Fused kernel (R11 structure, register diet): phase1 10 steps with per-step
// objective reduce to smem (no o[11] in regs, no y0 carry), smem anchors at
// steps 3/7, last-block warp-parallel decide, bounded poll, anchor-based emit.
// 256 blocks all resident (launch_bounds(256,2) -> 296 capacity) -> poll safe.
__global__ void __launch_bounds__(NTH, 2)
k_all(const float* __restrict__ xin, const float* __restrict__ yin,
      float* __restrict__ out, int B, int nblk) {
    int tid  = threadIdx.x;
    int base = blockIdx.x * PROB_PER_BLK + tid;
    int b0 = base, b1 = base + NTH, b2 = base + 2 * NTH, b3 = base + 3 * NTH;
    int lane = tid & 31;
    int wid  = tid >> 5;

    __shared__ float4 anch[2][4 * NTH];   // 32KB: (x1,x2,al,be) after steps 3, 7
    __shared__ float  sm[(NTH / 32)][11];
    __shared__ int    s_epoch, s_is_last, s_K;

    // ---- phase 1: 10 GN steps, 2 independent packed chains ----
    u64 Ax1, Ax2, AS1, AS2, Aal = ONE2, Abe = 0;
    u64 Bx1, Bx2, BS1, BS2, Bal = ONE2, Bbe = 0;
    bool va0, va1, vb0, vb1;
    load_x(xin, b0, b1, B, Ax1, Ax2, va0, va1);
    load_x(xin, b2, b3, B, Bx1, Bx2, vb0, vb1);
    {   // derive S1,S2 from y0, then y0 regs die (reloaded in phase 2)
        u64 y1, y2, y3;
        load_y(yin, b0, b1, B, y1, y2, y3);
        AS1 = add2(add2(y1, y2), y3);
        AS2 = fma2(y1, y1, fma2(y2, y2, mul2(y3, y3)));
        load_y(yin, b2, b3, B, y1, y2, y3);
        BS1 = add2(add2(y1, y2), y3);
        BS2 = fma2(y1, y1, fma2(y2, y2, mul2(y3, y3)));
    }

#pragma unroll
    for (int t = 0; t < 10; t++) {
        u64 oa = gn2(Ax1, Ax2, AS1, AS2, Aal, Abe);
        u64 ob = gn2(Bx1, Bx2, BS1, BS2, Bal, Bbe);
        // per-step reduce: only one objective value live at a time
        float v = masked_sum(oa, va0, va1) + masked_sum(ob, vb0, vb1);
#pragma unroll
        for (int off = 16; off > 0; off >>= 1)
            v += __shfl_down_sync(0xffffffffu, v, off);
        if (lane == 0) sm[wid][t] = v;
        if (t == 2 || t == 6) {           // state after steps 3 / 7
            int a = (t == 2) ? 0 : 1;
            float p, q, r, s, p2, q2, r2, s2;
            unpack2(Ax1, p, p2); unpack2(Ax2, q, q2);
            unpack2(Aal, r, r2); unpack2(Abe, s, s2);
            anch[a][tid]           = make_float4(p,  q,  r,  s);
            anch[a][tid + NTH]     = make_float4(p2, q2, r2, s2);
            unpack2(Bx1, p, p2); unpack2(Bx2, q, q2);
            unpack2(Bal, r, r2); unpack2(Bbe, s, s2);
            anch[a][tid + 2 * NTH] = make_float4(p,  q,  r,  s);
            anch[a][tid + 3 * NTH] = make_float4(p2, q2, r2, s2);
        }
    }
    {
        float v = masked_sum(obj_state(Ax1, Ax2, AS1, AS2), va0, va1)
                + masked_sum(obj_state(Bx1, Bx2, BS1, BS2), vb0, vb1);
#pragma unroll
        for (int off = 16; off > 0; off >>= 1)
            v += __shfl_down_sync(0xffffffffu, v, off);
        if (lane == 0) sm[wid][10] = v;
    }
    __syncthreads();
    if (wid == 0) {
#pragma unroll
        for (int t = 0; t < 11; t++) {
            float w = (lane < (NTH / 32)) ? sm[lane][t] : 0.f;
#pragma unroll
            for (int off = 4; off > 0; off >>= 1)
                w += __shfl_down_sync(0xffffffffu, w, off);
            if (lane == 0) g_part[t * MAXBLK + blockIdx.x] = (double)w;
        }
    }

    // ---- arrival; last block decides K (warp-parallel reduce) ----
    __threadfence();
    if (tid == 0) {
        int old = atomicAdd(&g_arrive, 1);
        s_epoch   = old / nblk;
        s_is_last = ((old % nblk) == (nblk - 1));
    }
    __syncthreads();
    int epoch = s_epoch;

    if (s_is_last) {
        __shared__ double osum[11];
        for (int t = wid; t < 11; t += (NTH / 32)) {
            double s0 = 0.0, s1 = 0.0;
            int i = lane;
            for (; i + 32 < nblk; i += 64) {
                s0 += g_part[t * MAXBLK + i];
                s1 += g_part[t * MAXBLK + i + 32];
            }
            if (i < nblk) s0 += g_part[t * MAXBLK + i];
            double s = s0 + s1;
#pragma unroll
            for (int off = 16; off > 0; off >>= 1)
                s += __shfl_down_sync(0xffffffffu, s, off);
            if (lane == 0) osum[t] = s;
        }
        __syncthreads();
        if (tid == 0) {
            double obj = osum[0];
            int K = 0;
            for (int t = 1; t <= 10; t++) {
                if (osum[t] < obj) { obj = osum[t]; K = t; }
                else break;   // reject freezes the state (reg is a fp32 no-op)
            }
            atomicExch(&g_flag, (epoch + 1) * 16 + K);   // monotone publish
        }
    }

    // ---- bounded poll for the decision ----
    int target = (epoch + 1) * 16;
    if (tid == 0) {
        int f = *(volatile int*)&g_flag;
        int spins = 0;
        while (f < target && spins < 200000) {
            __nanosleep(32);
            f = *(volatile int*)&g_flag;
            spins++;
        }
        s_K = (f >= target) ? (f - target) : 10;   // escape hatch
    }
    __syncthreads();
    int K = s_K;

    // ---- phase 2: emit s_K (at most 3 gn2 steps from an anchor) ----
    u64 Ay1, Ay2, Ay3, By1, By2, By3;
    load_y(yin, b0, b1, B, Ay1, Ay2, Ay3);     // L2-hot reload
    load_y(yin, b2, b3, B, By1, By2, By3);

    if (K < 10) {
        int extra;
        if (K >= 7) {
            float4 cA0 = anch[1][tid],           cA1 = anch[1][tid + NTH];
            float4 cB0 = anch[1][tid + 2 * NTH], cB1 = anch[1][tid + 3 * NTH];
            Ax1 = pack2(cA0.x, cA1.x); Ax2 = pack2(cA0.y, cA1.y);
            Aal = pack2(cA0.z, cA1.z); Abe = pack2(cA0.w, cA1.w);
            Bx1 = pack2(cB0.x, cB1.x); Bx2 = pack2(cB0.y, cB1.y);
            Bal = pack2(cB0.z, cB1.z); Bbe = pack2(cB0.w, cB1.w);
            extra = K - 7;
        } else if (K >= 3) {
            float4 cA0 = anch[0][tid],           cA1 = anch[0][tid + NTH];
            float4 cB0 = anch[0][tid + 2 * NTH], cB1 = anch[0][tid + 3 * NTH];
            Ax1 = pack2(cA0.x, cA1.x); Ax2 = pack2(cA0.y, cA1.y);
            Aal = pack2(cA0.z, cA1.z); Abe = pack2(cA0.w, cA1.w);
            Bx1 = pack2(cB0.x, cB1.x); Bx2 = pack2(cB0.y, cB1.y);
            Bal = pack2(cB0.z, cB1.z); Bbe = pack2(cB0.w, cB1.w);
            extra = K - 3;
        } else {
            bool t0, t1;
            load_x(xin, b0, b1, B, Ax1, Ax2, t0, t1);
            load_x(xin, b2, b3, B, Bx1, Bx2, t0, t1);
            Aal = ONE2; Abe = 0; Bal = ONE2; Bbe = 0;
            extra = K;
        }
        if (extra > 0) {
            u64 ty1 = fma2(Aal, Ay1, Abe), ty2 = fma2(Aal, Ay2, Abe), ty3 = fma2(Aal, Ay3, Abe);
            AS1 = add2(add2(ty1, ty2), ty3);
            AS2 = fma2(ty1, ty1, fma2(ty2, ty2, mul2(ty3, ty3)));
            ty1 = fma2(Bal, By1, Bbe); ty2 = fma2(Bal, By2, Bbe); ty3 = fma2(Bal, By3, Bbe);
            BS1 = add2(add2(ty1, ty2), ty3);
            BS2 = fma2(ty1, ty1, fma2(ty2, ty2, mul2(ty3, ty3)));
            for (int e = 0; e < extra; e++) {
                gn2(Ax1, Ax2, AS1, AS2, Aal, Abe);
                gn2(Bx1, Bx2, BS1, BS2, Bal, Bbe);
            }
        }
    }

    Ay1 = fma2(Aal, Ay1, Abe); Ay2 = fma2(Aal, Ay2, Abe); Ay3 = fma2(Aal, Ay3, Abe);
    By1 = fma2(Bal, By1, Bbe); By2 = fma2(Bal, By2, Bbe); By3 = fma2(Bal, By3, Bbe);
    store_chain(out, B, b0, b1, va0, va1, Ax1, Ax2, Ay1, Ay2, Ay3);
    store_chain(out, B, b2, b3, vb0, vb1, Bx1, Bx2, By1, By2, By3);
}

extern "C" void kernel_launch(void* const* d_in, const int* in_sizes, int n_in,
                              void* d_out, int out_size) {
    const float* x = (const float*)d_in[0];   // (B,1,2) float32
    const float* y = (const float*)d_in[1];   // (B,3,1) float32
    int B = in_sizes[0] / 2;
    int nblk = (B + PROB_PER_BLK - 1) / PROB_PER_BLK;   // 256 for B=262144
    if (nblk > MAXBLK) nblk = MAXBLK;

    k_all<<<nblk, NTH>>>(x, y, (float*)d_out, B, nblk);
}

// round 16
// speedup vs baseline: 1.4665x; 1.2254x over previous
#include <cuda_runtime.h>

#define NTH 256
#define PROB_PER_BLK (NTH * 4)     // 1024
#define MAXBLK 4096

typedef unsigned long long u64;

__device__ double g_part[11 * MAXBLK];
__device__ double g_osum5;         // reduced o_5, handed from decide A to decide B
__device__ int    g_arriveA;       // monotone across graph replays
__device__ int    g_arriveB;
__device__ int    g_flagA;         // (epochA+1)*16 + code ; code 0..4 = K, 15 = continue
__device__ int    g_flagB;         // (epochB+1)*16 + (K-5) ; K in 5..10

// ---------- packed f32x2 primitives (sm_100+) ----------
__device__ __forceinline__ u64 fma2(u64 a, u64 b, u64 c) {
    u64 d; asm("fma.rn.f32x2 %0, %1, %2, %3;" : "=l"(d) : "l"(a), "l"(b), "l"(c)); return d;
}
__device__ __forceinline__ u64 mul2(u64 a, u64 b) {
    u64 d; asm("mul.rn.f32x2 %0, %1, %2;" : "=l"(d) : "l"(a), "l"(b)); return d;
}
__device__ __forceinline__ u64 add2(u64 a, u64 b) {
    u64 d; asm("add.rn.f32x2 %0, %1, %2;" : "=l"(d) : "l"(a), "l"(b)); return d;
}
__device__ __forceinline__ u64 neg2(u64 a) { return a ^ 0x8000000080000000ull; }
__device__ __forceinline__ u64 sub2(u64 a, u64 b) { return add2(a, neg2(b)); }

__device__ __forceinline__ u64 pack2(float lo, float hi) {
    u64 d; asm("mov.b64 %0, {%1, %2};" : "=l"(d) : "f"(lo), "f"(hi)); return d;
}
__device__ __forceinline__ void unpack2(u64 a, float& lo, float& hi) {
    asm("mov.b64 {%0, %1}, %2;" : "=f"(lo), "=f"(hi) : "l"(a));
}
__device__ __forceinline__ float frcp(float a) {
    float r; asm("rcp.approx.f32 %0, %1;" : "=f"(r) : "f"(a)); return r;
}
__device__ __forceinline__ u64 rcp2(u64 a) {
    float lo, hi; unpack2(a, lo, hi);
    return pack2(frcp(lo), frcp(hi));
}

#define C3   0x4040000040400000ull   // {3.0f, 3.0f}
#define C2   0x4000000040000000ull   // {2.0f, 2.0f}
#define ONE2 0x3F8000003F800000ull   // {1.0f, 1.0f}

// y-free packed GN step, single rcp on the critical path (Bv-scaled Schur).
// Carries (x1,x2,S1,S2) + affine y-coeffs (al,be): y_t = al*y0 + be.
// Returns packed objective at the INPUT state: 3Q + 2(P1*S1 + S2) + Q*S2.
__device__ __forceinline__ u64 gn2(u64& x1, u64& x2, u64& S1, u64& S2,
                                   u64& al, u64& be) {
    u64 Q  = fma2(x1, x1, mul2(x2, x2));
    u64 P1 = add2(x1, x2);
    u64 obj = fma2(Q, S2, fma2(C2, fma2(P1, S1, S2), mul2(C3, Q)));

    u64 A  = add2(S2, C3);
    u64 Bv = add2(Q, C2);
    u64 t  = rcp2(Bv);                  // parallel to the M/det chain

    u64 q1 = fma2(S1, x1, C3);
    u64 q2 = fma2(S1, x2, C3);
    u64 a1 = fma2(S2, x1, S1);
    u64 a2 = fma2(S2, x2, S1);

    u64 cc11 = fma2(a1, x1, q1);
    u64 cc12 = fma2(a1, x2, q1);
    u64 cc22 = fma2(a2, x2, q2);

    u64 AB  = mul2(A, Bv);
    u64 m11 = sub2(AB, cc11);
    u64 m22 = sub2(AB, cc22);

    u64 B3  = mul2(C3, Bv);
    u64 P1n = neg2(P1);
    u64 r1 = fma2(B3, x1, mul2(P1n, q1));
    u64 r2 = fma2(B3, x2, mul2(P1n, q2));

    u64 detM = fma2(m11, m22, neg2(mul2(cc12, cc12)));
    u64 i    = rcp2(detM);              // the ONE rcp on the critical path

    u64 ux1 = mul2(fma2(m22, r1, mul2(cc12, r2)), i);
    u64 ux2 = mul2(fma2(m11, r2, mul2(cc12, r1)), i);

    u64 Su = add2(ux1, ux2);
    u64 xu = fma2(x1, ux1, mul2(x2, ux2));   // uses OLD x
    x1 = sub2(x1, ux1);
    x2 = sub2(x2, ux2);

    u64 c   = add2(Su, P1n);
    u64 txu = mul2(t, xu);
    u64 tc  = mul2(t, c);

    al = mul2(txu, al);
    be = fma2(txu, be, tc);

    u64 S1n = fma2(txu, S1, mul2(C3, tc));
    u64 S2n = fma2(txu, fma2(txu, S2, mul2(mul2(C2, tc), S1)),
                   mul2(C3, mul2(tc, tc)));
    S1 = S1n; S2 = S2n;
    return obj;
}

__device__ __forceinline__ u64 obj_state(u64 x1, u64 x2, u64 S1, u64 S2) {
    u64 Q  = fma2(x1, x1, mul2(x2, x2));
    u64 P1 = add2(x1, x2);
    return fma2(Q, S2, fma2(C2, fma2(P1, S1, S2), mul2(C3, Q)));
}

__device__ __forceinline__ void load_x(const float* __restrict__ xin,
                                       int b0, int b1, int B,
                                       u64& x1, u64& x2, bool& v0, bool& v1) {
    v0 = (b0 < B); v1 = (b1 < B);
    float ax1 = 1.f, ax2 = 0.f, bx1 = 1.f, bx2 = 0.f;
    if (v0) { float2 xv = *reinterpret_cast<const float2*>(xin + 2 * b0); ax1 = xv.x; ax2 = xv.y; }
    if (v1) { float2 xv = *reinterpret_cast<const float2*>(xin + 2 * b1); bx1 = xv.x; bx2 = xv.y; }
    x1 = pack2(ax1, bx1); x2 = pack2(ax2, bx2);
}
__device__ __forceinline__ void load_y(const float* __restrict__ yin,
                                       int b0, int b1, int B,
                                       u64& y1, u64& y2, u64& y3) {
    float ay1 = 1.f, ay2 = 0.f, ay3 = 0.f, by1 = 1.f, by2 = 0.f, by3 = 0.f;
    if (b0 < B) { ay1 = yin[3 * b0]; ay2 = yin[3 * b0 + 1]; ay3 = yin[3 * b0 + 2]; }
    if (b1 < B) { by1 = yin[3 * b1]; by2 = yin[3 * b1 + 1]; by3 = yin[3 * b1 + 2]; }
    y1 = pack2(ay1, by1); y2 = pack2(ay2, by2); y3 = pack2(ay3, by3);
}

__device__ __forceinline__ float masked_sum(u64 o, bool v0, bool v1) {
    float lo, hi; unpack2(o, lo, hi);
    return (v0 ? lo : 0.f) + (v1 ? hi : 0.f);
}

__device__ __forceinline__ void store_chain(float* __restrict__ out, int B,
                                            int b0, int b1, bool v0, bool v1,
                                            u64 x1, u64 x2, u64 y1, u64 y2, u64 y3) {
    float lx1, lx2, ly1, ly2, ly3, hx1, hx2, hy1, hy2, hy3;
    unpack2(x1, lx1, hx1); unpack2(x2, lx2, hx2);
    unpack2(y1, ly1, hy1); unpack2(y2, ly2, hy2); unpack2(y3, ly3, hy3);
    if (v0) {
        out[2 * b0] = lx1; out[2 * b0 + 1] = lx2;
        out[2 * B + 3 * b0] = ly1; out[2 * B + 3 * b0 + 1] = ly2; out[2 * B + 3 * b0 + 2] = ly3;
    }
    if (v1) {
        out[2 * b1] = hx1; out[2 * b1 + 1] = hx2;
        out[2 * B + 3 * b1] = hy1; out[2 * B + 3 * b1 + 1] = hy2; out[2 * B + 3 * b1 + 2] = hy3;
    }
}

// Two-stage fused kernel on the lean R15 skeleton: per-step objective reduce
// (no o arrays), no y0 carry, smem anchors at steps 3/7. Stage A = 5 steps +
// decide over o_0..o_5; K<=4 -> emit immediately (skip steps 6..10). Else
// stage B = 5 more steps + second decide.
// 256 blocks all resident (launch_bounds(256,2) -> 296 capacity) -> polls safe.
__global__ void __launch_bounds__(NTH, 2)
k_all(const float* __restrict__ xin, const float* __restrict__ yin,
      float* __restrict__ out, int B, int nblk) {
    int tid  = threadIdx.x;
    int base = blockIdx.x * PROB_PER_BLK + tid;
    int b0 = base, b1 = base + NTH, b2 = base + 2 * NTH, b3 = base + 3 * NTH;
    int lane = tid & 31;
    int wid  = tid >> 5;

    __shared__ float4 anch[2][4 * NTH];   // 32KB: (x1,x2,al,be) after steps 3, 7
    __shared__ float  sm[(NTH / 32)][6];
    __shared__ int    s_epoch, s_is_last, s_code;

    // ---- stage A: 5 GN steps, 2 independent packed chains ----
    u64 Ax1, Ax2, AS1, AS2, Aal = ONE2, Abe = 0;
    u64 Bx1, Bx2, BS1, BS2, Bal = ONE2, Bbe = 0;
    bool va0, va1, vb0, vb1;
    load_x(xin, b0, b1, B, Ax1, Ax2, va0, va1);
    load_x(xin, b2, b3, B, Bx1, Bx2, vb0, vb1);
    {   // derive S1,S2 from y0, then the y0 regs die (reloaded in the emit)
        u64 y1, y2, y3;
        load_y(yin, b0, b1, B, y1, y2, y3);
        AS1 = add2(add2(y1, y2), y3);
        AS2 = fma2(y1, y1, fma2(y2, y2, mul2(y3, y3)));
        load_y(yin, b2, b3, B, y1, y2, y3);
        BS1 = add2(add2(y1, y2), y3);
        BS2 = fma2(y1, y1, fma2(y2, y2, mul2(y3, y3)));
    }

#pragma unroll
    for (int t = 0; t < 5; t++) {
        u64 oa = gn2(Ax1, Ax2, AS1, AS2, Aal, Abe);
        u64 ob = gn2(Bx1, Bx2, BS1, BS2, Bal, Bbe);
        float v = masked_sum(oa, va0, va1) + masked_sum(ob, vb0, vb1);
#pragma unroll
        for (int off = 16; off > 0; off >>= 1)
            v += __shfl_down_sync(0xffffffffu, v, off);
        if (lane == 0) sm[wid][t] = v;
        if (t == 2) {                     // state after step 3
            float p, q, r, s, p2, q2, r2, s2;
            unpack2(Ax1, p, p2); unpack2(Ax2, q, q2);
            unpack2(Aal, r, r2); unpack2(Abe, s, s2);
            anch[0][tid]           = make_float4(p,  q,  r,  s);
            anch[0][tid + NTH]     = make_float4(p2, q2, r2, s2);
            unpack2(Bx1, p, p2); unpack2(Bx2, q, q2);
            unpack2(Bal, r, r2); unpack2(Bbe, s, s2);
            anch[0][tid + 2 * NTH] = make_float4(p,  q,  r,  s);
            anch[0][tid + 3 * NTH] = make_float4(p2, q2, r2, s2);
        }
    }
    {
        float v = masked_sum(obj_state(Ax1, Ax2, AS1, AS2), va0, va1)
                + masked_sum(obj_state(Bx1, Bx2, BS1, BS2), vb0, vb1);
#pragma unroll
        for (int off = 16; off > 0; off >>= 1)
            v += __shfl_down_sync(0xffffffffu, v, off);
        if (lane == 0) sm[wid][5] = v;
    }
    __syncthreads();
    if (wid == 0) {
#pragma unroll
        for (int t = 0; t < 6; t++) {
            float w = (lane < (NTH / 32)) ? sm[lane][t] : 0.f;
#pragma unroll
            for (int off = 4; off > 0; off >>= 1)
                w += __shfl_down_sync(0xffffffffu, w, off);
            if (lane == 0) g_part[t * MAXBLK + blockIdx.x] = (double)w;
        }
    }

    // ---- arrival A; last block decides the prefix ----
    __threadfence();
    if (tid == 0) {
        int old = atomicAdd(&g_arriveA, 1);
        s_epoch   = old / nblk;
        s_is_last = ((old % nblk) == (nblk - 1));
    }
    __syncthreads();
    int epochA = s_epoch;

    if (s_is_last) {
        __shared__ double osum[6];
        for (int t = wid; t < 6; t += (NTH / 32)) {
            double s0 = 0.0, s1 = 0.0;
            int i = lane;
            for (; i + 32 < nblk; i += 64) {
                s0 += g_part[t * MAXBLK + i];
                s1 += g_part[t * MAXBLK + i + 32];
            }
            if (i < nblk) s0 += g_part[t * MAXBLK + i];
            double s = s0 + s1;
#pragma unroll
            for (int off = 16; off > 0; off >>= 1)
                s += __shfl_down_sync(0xffffffffu, s, off);
            if (lane == 0) osum[t] = s;
        }
        __syncthreads();
        if (tid == 0) {
            int code = 15;                       // continue sentinel
            double prev = osum[0];
            for (int t = 1; t <= 5; t++) {
                if (!(osum[t] < prev)) { code = t - 1; break; }
                prev = osum[t];
            }
            g_osum5 = osum[5];
            __threadfence();
            atomicExch(&g_flagA, (epochA + 1) * 16 + code);
        }
    }

    // ---- bounded poll A ----
    if (tid == 0) {
        int target = (epochA + 1) * 16;
        int f = *(volatile int*)&g_flagA;
        int spins = 0;
        while (f < target && spins < 400000) {
            __nanosleep(32);
            f = *(volatile int*)&g_flagA;
            spins++;
        }
        s_code = (f >= target) ? (f - target) : 15;   // timeout -> continue (safe)
    }
    __syncthreads();

    int K;
    if (s_code <= 4) {
        K = s_code;                                   // early exit: skip steps 6..10
    } else {
        // ---- stage B: steps 6..10, per-step reduce (rows 6..10) ----
#pragma unroll
        for (int e = 0; e < 5; e++) {
            u64 oa = gn2(Ax1, Ax2, AS1, AS2, Aal, Abe);
            u64 ob = gn2(Bx1, Bx2, BS1, BS2, Bal, Bbe);
            if (e > 0) {                  // returns o_{5+e}; e=0's o_5 already counted
                float v = masked_sum(oa, va0, va1) + masked_sum(ob, vb0, vb1);
#pragma unroll
                for (int off = 16; off > 0; off >>= 1)
                    v += __shfl_down_sync(0xffffffffu, v, off);
                if (lane == 0) sm[wid][e - 1] = v;
            }
            if (e == 1) {                 // state after step 7
                float p, q, r, s, p2, q2, r2, s2;
                unpack2(Ax1, p, p2); unpack2(Ax2, q, q2);
                unpack2(Aal, r, r2); unpack2(Abe, s, s2);
                anch[1][tid]           = make_float4(p,  q,  r,  s);
                anch[1][tid + NTH]     = make_float4(p2, q2, r2, s2);
                unpack2(Bx1, p, p2); unpack2(Bx2, q, q2);
                unpack2(Bal, r, r2); unpack2(Bbe, s, s2);
                anch[1][tid + 2 * NTH] = make_float4(p,  q,  r,  s);
                anch[1][tid + 3 * NTH] = make_float4(p2, q2, r2, s2);
            }
        }
        {
            float v = masked_sum(obj_state(Ax1, Ax2, AS1, AS2), va0, va1)
                    + masked_sum(obj_state(Bx1, Bx2, BS1, BS2), vb0, vb1);
#pragma unroll
            for (int off = 16; off > 0; off >>= 1)
                v += __shfl_down_sync(0xffffffffu, v, off);
            if (lane == 0) sm[wid][4] = v;    // row index 4 -> o_10
        }
        __syncthreads();
        if (wid == 0) {
#pragma unroll
            for (int t = 0; t < 5; t++) {     // rows 0..4 -> o_6..o_10
                float w = (lane < (NTH / 32)) ? sm[lane][t] : 0.f;
#pragma unroll
                for (int off = 4; off > 0; off >>= 1)
                    w += __shfl_down_sync(0xffffffffu, w, off);
                if (lane == 0) g_part[(6 + t) * MAXBLK + blockIdx.x] = (double)w;
            }
        }

        __threadfence();
        if (tid == 0) {
            int old = atomicAdd(&g_arriveB, 1);
            s_epoch   = old / nblk;
            s_is_last = ((old % nblk) == (nblk - 1));
        }
        __syncthreads();
        int epochB = s_epoch;

        if (s_is_last) {
            __shared__ double osum[5];
            for (int t = wid; t < 5; t += (NTH / 32)) {
                double s0 = 0.0, s1 = 0.0;
                int i = lane;
                for (; i + 32 < nblk; i += 64) {
                    s0 += g_part[(6 + t) * MAXBLK + i];
                    s1 += g_part[(6 + t) * MAXBLK + i + 32];
                }
                if (i < nblk) s0 += g_part[(6 + t) * MAXBLK + i];
                double s = s0 + s1;
#pragma unroll
                for (int off = 16; off > 0; off >>= 1)
                    s += __shfl_down_sync(0xffffffffu, s, off);
                if (lane == 0) osum[t] = s;
            }
            __syncthreads();
            if (tid == 0) {
                double prev = g_osum5;            // ordered via flagA handoff
                int Kd = 10;
                for (int t = 0; t < 5; t++) {     // osum[t] = o_{6+t}
                    if (!(osum[t] < prev)) { Kd = 5 + t; break; }
                    prev = osum[t];
                }
                atomicExch(&g_flagB, (epochB + 1) * 16 + (Kd - 5));
            }
        }

        if (tid == 0) {
            int target = (epochB + 1) * 16;
            int f = *(volatile int*)&g_flagB;
            int spins = 0;
            while (f < target && spins < 400000) {
                __nanosleep(32);
                f = *(volatile int*)&g_flagB;
                spins++;
            }
            s_code = (f >= target) ? (f - target) : 5;   // timeout -> K=10
        }
        __syncthreads();
        K = 5 + s_code;
    }

    // ---- emit s_K ----
    u64 Ay1, Ay2, Ay3, By1, By2, By3;
    load_y(yin, b0, b1, B, Ay1, Ay2, Ay3);     // L2-hot reload
    load_y(yin, b2, b3, B, By1, By2, By3);

    if (K < 10) {
        int extra;
        if (K >= 7) {
            float4 cA0 = anch[1][tid],           cA1 = anch[1][tid + NTH];
            float4 cB0 = anch[1][tid + 2 * NTH], cB1 = anch[1][tid + 3 * NTH];
            Ax1 = pack2(cA0.x, cA1.x); Ax2 = pack2(cA0.y, cA1.y);
            Aal = pack2(cA0.z, cA1.z); Abe = pack2(cA0.w, cA1.w);
            Bx1 = pack2(cB0.x, cB1.x); Bx2 = pack2(cB0.y, cB1.y);
            Bal = pack2(cB0.z, cB1.z); Bbe = pack2(cB0.w, cB1.w);
            extra = K - 7;
        } else if (K >= 3) {
            float4 cA0 = anch[0][tid],           cA1 = anch[0][tid + NTH];
            float4 cB0 = anch[0][tid + 2 * NTH], cB1 = anch[0][tid + 3 * NTH];
            Ax1 = pack2(cA0.x, cA1.x); Ax2 = pack2(cA0.y, cA1.y);
            Aal = pack2(cA0.z, cA1.z); Abe = pack2(cA0.w, cA1.w);
            Bx1 = pack2(cB0.x, cB1.x); Bx2 = pack2(cB0.y, cB1.y);
            Bal = pack2(cB0.z, cB1.z); Bbe = pack2(cB0.w, cB1.w);
            extra = K - 3;
        } else {
            bool t0, t1;
            load_x(xin, b0, b1, B, Ax1, Ax2, t0, t1);
            load_x(xin, b2, b3, B, Bx1, Bx2, t0, t1);
            Aal = ONE2; Abe = 0; Bal = ONE2; Bbe = 0;
            extra = K;
        }
        if (extra > 0) {
            u64 ty1 = fma2(Aal, Ay1, Abe), ty2 = fma2(Aal, Ay2, Abe), ty3 = fma2(Aal, Ay3, Abe);
            AS1 = add2(add2(ty1, ty2), ty3);
            AS2 = fma2(ty1, ty1, fma2(ty2, ty2, mul2(ty3, ty3)));
            ty1 = fma2(Bal, By1, Bbe); ty2 = fma2(Bal, By2, Bbe); ty3 = fma2(Bal, By3, Bbe);
            BS1 = add2(add2(ty1, ty2), ty3);
            BS2 = fma2(ty1, ty1, fma2(ty2, ty2, mul2(ty3, ty3)));
            for (int e = 0; e < extra; e++) {
                gn2(Ax1, Ax2, AS1, AS2, Aal, Abe);
                gn2(Bx1, Bx2, BS1, BS2, Bal, Bbe);
            }
        }
    }

    Ay1 = fma2(Aal, Ay1, Abe); Ay2 = fma2(Aal, Ay2, Abe); Ay3 = fma2(Aal, Ay3, Abe);
    By1 = fma2(Bal, By1, Bbe); By2 = fma2(Bal, By2, Bbe); By3 = fma2(Bal, By3, Bbe);
    store_chain(out, B, b0, b1, va0, va1, Ax1, Ax2, Ay1, Ay2, Ay3);
    store_chain(out, B, b2, b3, vb0, vb1, Bx1, Bx2, By1, By2, By3);
}

extern "C" void kernel_launch(void* const* d_in, const int* in_sizes, int n_in,
                              void* d_out, int out_size) {
    const float* x = (const float*)d_in[0];   // (B,1,2) float32
    const float* y = (const float*)d_in[1];   // (B,3,1) float32
    int B = in_sizes[0] / 2;
    int nblk = (B + PROB_PER_BLK - 1) / PROB_PER_BLK;   // 256 for B=262144
    if (nblk > MAXBLK) nblk = MAXBLK;

    k_all<<<nblk, NTH>>>(x, y, (float*)d_out, B, nblk);
}